// round 14
// baseline (speedup 1.0000x reference)
#include <cuda_runtime.h>
#include <cuda_fp16.h>
#include <cuda_bf16.h>
#include <math.h>
#include <stdint.h>

#define NB 4
#define NT 2048
#define ND 1024
#define NH 16
#define NHD 64

#define QSCALE 0.1803368801111244f   // 0.125 * log2(e)
#define LOG2E  1.4426950408889634f

// ---------------------------------------------------------------------------
// scratch (allocation-free rule: __device__ globals) — plain fp16 everywhere
// ---------------------------------------------------------------------------
__device__ __align__(256) __half g_x_h[(size_t)NB * NT * ND];
__device__ __align__(256) __half g_wq_h[(size_t)3 * ND * ND];     // Wqkv^T [3D, D]
__device__ __align__(256) __half g_wo_h[(size_t)ND * ND];         // Wout^T [D, D]
__device__ __align__(256) __half g_att_h[(size_t)NB * NT * ND];
// per-head q/k/v: [B,H,T,64] fp16 (q pre-scaled by QSCALE)
__device__ __align__(256) __half g_q_h[(size_t)NB * NH * NT * NHD];
__device__ __align__(256) __half g_k_h[(size_t)NB * NH * NT * NHD];
__device__ __align__(256) __half g_v_h[(size_t)NB * NH * NT * NHD];
// entity bias in bf16, pre-multiplied by log2(e)
__device__ __align__(256) __nv_bfloat16 g_eb_bf[(size_t)NB * NT * NT];

// ---------------------------------------------------------------------------
// PTX helpers (all baseline sm_80+)
// ---------------------------------------------------------------------------
__device__ __forceinline__ uint32_t smem_u32(const void* p) {
    uint32_t a;
    asm("{ .reg .u64 t; cvta.to.shared.u64 t, %1; cvt.u32.u64 %0, t; }" : "=r"(a) : "l"(p));
    return a;
}
__device__ __forceinline__ void ldsm4(uint32_t* r, uint32_t addr) {
    asm volatile("ldmatrix.sync.aligned.m8n8.x4.shared.b16 {%0,%1,%2,%3}, [%4];"
                 : "=r"(r[0]), "=r"(r[1]), "=r"(r[2]), "=r"(r[3]) : "r"(addr));
}
__device__ __forceinline__ void ldsm4t(uint32_t* r, uint32_t addr) {
    asm volatile("ldmatrix.sync.aligned.m8n8.x4.trans.shared.b16 {%0,%1,%2,%3}, [%4];"
                 : "=r"(r[0]), "=r"(r[1]), "=r"(r[2]), "=r"(r[3]) : "r"(addr));
}
__device__ __forceinline__ void mma_f16(float* c, const uint32_t* a, const uint32_t* b) {
    asm volatile(
        "mma.sync.aligned.m16n8k16.row.col.f32.f16.f16.f32 "
        "{%0,%1,%2,%3}, {%4,%5,%6,%7}, {%8,%9}, {%0,%1,%2,%3};"
        : "+f"(c[0]), "+f"(c[1]), "+f"(c[2]), "+f"(c[3])
        : "r"(a[0]), "r"(a[1]), "r"(a[2]), "r"(a[3]), "r"(b[0]), "r"(b[1]));
}
__device__ __forceinline__ void cp16(uint32_t smem, const void* g) {
    asm volatile("cp.async.cg.shared.global [%0], [%1], 16;" :: "r"(smem), "l"(g));
}
#define CP_COMMIT() asm volatile("cp.async.commit_group;" ::: "memory")
#define CP_WAIT1()  asm volatile("cp.async.wait_group 1;" ::: "memory")
#define CP_WAIT0()  asm volatile("cp.async.wait_group 0;" ::: "memory")

__device__ __forceinline__ float fexp2(float x) {
    float r;
    asm("ex2.approx.f32 %0, %1;" : "=f"(r) : "f"(x));
    return r;
}
__device__ __forceinline__ uint32_t packh(float a, float b) {
    __half2 t = __floats2half2_rn(a, b);
    return *reinterpret_cast<uint32_t*>(&t);
}
__device__ __forceinline__ uint32_t packbf(float a, float b) {
    __nv_bfloat162 t = __float22bfloat162_rn(make_float2(a, b));
    return *reinterpret_cast<uint32_t*>(&t);
}

// ---------------------------------------------------------------------------
// fused prepass: x -> fp16 + both weight transposes (fp16)
// ---------------------------------------------------------------------------
#define BLK_SPLIT 32768
#define BLK_TQKV  3072
#define BLK_TWO   1024

__global__ __launch_bounds__(256)
void prepass_kernel(const float* __restrict__ x,
                    const float* __restrict__ Wqkv,
                    const float* __restrict__ Wout,
                    __half* __restrict__ xh,
                    __half* __restrict__ wqh, __half* __restrict__ woh)
{
    __shared__ float t[32][33];
    const int bid = blockIdx.x;
    const int tid = threadIdx.x;

    if (bid < BLK_SPLIT) {
        const int i = bid * 256 + tid;
        xh[i] = __float2half_rn(x[i]);
        return;
    }

    const float* W;
    __half* Th;
    int N, tb;
    if (bid < BLK_SPLIT + BLK_TQKV) {
        tb = bid - BLK_SPLIT; W = Wqkv; Th = wqh; N = 3 * ND;
    } else {
        tb = bid - BLK_SPLIT - BLK_TQKV; W = Wout; Th = woh; N = ND;
    }
    const int K = ND;
    const int n0 = (tb % (N / 32)) * 32;
    const int k0 = (tb / (N / 32)) * 32;
    const int tx = tid & 31, ty = tid >> 5;
    #pragma unroll
    for (int j = 0; j < 32; j += 8)
        t[ty + j][tx] = W[(size_t)(k0 + ty + j) * N + n0 + tx];
    __syncthreads();
    #pragma unroll
    for (int j = 0; j < 32; j += 8)
        Th[(size_t)(n0 + ty + j) * K + k0 + tx] = __float2half_rn(t[tx][ty + j]);
}

// ---------------------------------------------------------------------------
// entity bias fp32 -> bf16 * log2(e)
// ---------------------------------------------------------------------------
__global__ __launch_bounds__(256)
void bias_to_bf16_kernel(const float* __restrict__ src, __nv_bfloat16* __restrict__ dst)
{
    const size_t i = ((size_t)blockIdx.x * 256 + threadIdx.x) * 4;
    const float4 v = *reinterpret_cast<const float4*>(src + i);
    uint32_t p0 = packbf(v.x * LOG2E, v.y * LOG2E);
    uint32_t p1 = packbf(v.z * LOG2E, v.w * LOG2E);
    *reinterpret_cast<uint32_t*>(dst + i)     = p0;
    *reinterpret_cast<uint32_t*>(dst + i + 2) = p1;
}

// ---------------------------------------------------------------------------
// fp16 GEMM (1 pass, proven R13): tile 128x128, BK=32, 3-stage, 2 CTAs/SM.
// ---------------------------------------------------------------------------
#define STG_BYTES 20480
#define T_AH 0
#define T_BH 10240

template <int MODE>
__global__ __launch_bounds__(256, 2)
void gemm_f16(const __half* __restrict__ Ah, const __half* __restrict__ Bh,
              const float* __restrict__ bias, float* __restrict__ C,
              __half* __restrict__ qh, __half* __restrict__ kh, __half* __restrict__ vh,
              int M, int N, int K)
{
    extern __shared__ char dynsm[];
    const uint32_t sb0 = smem_u32(dynsm);

    const int tid = threadIdx.x;
    const int wid = tid >> 5;
    const int l   = tid & 31;
    const int wm  = wid >> 1;
    const int wn  = wid & 1;
    const size_t m0 = (size_t)blockIdx.y * 128;
    const size_t n0 = (size_t)blockIdx.x * 128;

    const int r1 = tid >> 2;
    const int r2 = r1 + 64;
    const int cc = (tid & 3);
    const uint32_t sm_off1 = (uint32_t)r1 * 80 + cc * 16;
    const uint32_t sm_off2 = (uint32_t)r2 * 80 + cc * 16;

    const int nchunks = K >> 5;

    auto issue_stage = [&](int c, int buf) {
        const int kc = c << 5;
        const uint32_t sb = sb0 + buf * STG_BYTES;
        cp16(sb + T_AH + sm_off1, Ah + (m0 + r1) * K + kc + cc * 8);
        cp16(sb + T_AH + sm_off2, Ah + (m0 + r2) * K + kc + cc * 8);
        cp16(sb + T_BH + sm_off1, Bh + (n0 + r1) * K + kc + cc * 8);
        cp16(sb + T_BH + sm_off2, Bh + (n0 + r2) * K + kc + cc * 8);
        CP_COMMIT();
    };

    const int aRow = (l & 7) + ((l >> 3) & 1) * 8;
    const int aCol8 = (l >> 4) * 8;
    const int bRow = (l & 7) + ((l >> 4) & 1) * 8;
    const int bCol8 = ((l >> 3) & 1) * 8;

    float acc[2][8][4];
    #pragma unroll
    for (int mt = 0; mt < 2; mt++)
        #pragma unroll
        for (int nt = 0; nt < 8; nt++)
            #pragma unroll
            for (int k = 0; k < 4; k++) acc[mt][nt][k] = 0.f;

    issue_stage(0, 0);
    issue_stage(1, 1);

    for (int c = 0; c < nchunks; c++) {
        if (c == nchunks - 1) { CP_WAIT0(); } else { CP_WAIT1(); }
        __syncthreads();
        if (c + 2 < nchunks) issue_stage(c + 2, (c + 2) % 3);

        const uint32_t sb = sb0 + (c % 3) * STG_BYTES;
        const uint32_t aBase = sb + (uint32_t)(wm * 32 + aRow) * 80 + aCol8 * 2;
        const uint32_t bBase = sb + (uint32_t)(wn * 64 + bRow) * 80 + bCol8 * 2;

        #pragma unroll
        for (int ks = 0; ks < 2; ks++) {
            uint32_t ah[2][4];
            #pragma unroll
            for (int mt = 0; mt < 2; mt++)
                ldsm4(ah[mt], aBase + T_AH + mt * (16 * 80) + ks * 32);
            #pragma unroll
            for (int np = 0; np < 4; np++) {
                uint32_t bh[4];
                ldsm4(bh, bBase + T_BH + np * (16 * 80) + ks * 32);
                #pragma unroll
                for (int mt = 0; mt < 2; mt++)
                    #pragma unroll
                    for (int sub = 0; sub < 2; sub++)
                        mma_f16(acc[mt][np * 2 + sub], ah[mt], &bh[sub * 2]);
            }
        }
        __syncthreads();
    }

    if (MODE == 0) {
        #pragma unroll
        for (int mt = 0; mt < 2; mt++) {
            const size_t row0 = m0 + wm * 32 + mt * 16 + (l >> 2);
            #pragma unroll
            for (int nt = 0; nt < 8; nt++) {
                const size_t col = n0 + wn * 64 + nt * 8 + (l & 3) * 2;
                const float b0 = bias[col], b1 = bias[col + 1];
                float2 v0 = { acc[mt][nt][0] + b0, acc[mt][nt][1] + b1 };
                float2 v1 = { acc[mt][nt][2] + b0, acc[mt][nt][3] + b1 };
                *reinterpret_cast<float2*>(&C[row0 * N + col]) = v0;
                *reinterpret_cast<float2*>(&C[(row0 + 8) * N + col]) = v1;
            }
        }
    } else {
        const int colbase = (int)n0 + wn * 64;
        const int sel = colbase >> 10;             // 0=q,1=k,2=v
        const int head = (colbase >> 6) & 15;
        const float qs = (sel == 0) ? QSCALE : 1.0f;
        __half* dh = (sel == 0) ? qh : (sel == 1) ? kh : vh;
        #pragma unroll
        for (int mt = 0; mt < 2; mt++) {
            const int row0 = (int)m0 + wm * 32 + mt * 16 + (l >> 2);
            const int bb = row0 >> 11;
            const int t0 = row0 & 2047;
            const size_t base = ((size_t)(bb * NH + head) * NT + t0) * NHD;
            #pragma unroll
            for (int nt = 0; nt < 8; nt++) {
                const int col = colbase + nt * 8 + (l & 3) * 2;
                const int d = col & 63;
                const float b0 = bias[col], b1 = bias[col + 1];
                *reinterpret_cast<uint32_t*>(dh + base + d) =
                    packh((acc[mt][nt][0] + b0) * qs, (acc[mt][nt][1] + b1) * qs);
                *reinterpret_cast<uint32_t*>(dh + base + 8 * NHD + d) =
                    packh((acc[mt][nt][2] + b0) * qs, (acc[mt][nt][3] + b1) * qs);
            }
        }
    }
}

// ---------------------------------------------------------------------------
// fp16 flash attention — occupancy variant:
// 256 threads, 8 warps, warp M=16 (q-block 128), keytile 64, 1-pass.
// Low registers (~120) -> 2 CTAs/SM -> 16 warps/SM.
// smem: 2 x 18432 KV (Kh|Vh) + 18432 Q = 55296 B.
// ---------------------------------------------------------------------------
#define FROWB 144
#define KVARR (64 * FROWB)            // 9216
#define KVBUF (2 * KVARR)             // 18432 : Kh|Vh
#define QOFF (2 * KVBUF)              // 36864
#define FLASH_SMEM (QOFF + 128 * FROWB)   // 55296

__global__ __launch_bounds__(256, 2)
void flash_mma(const __half* __restrict__ qh, const __half* __restrict__ kh,
               const __half* __restrict__ vh,
               const __nv_bfloat16* __restrict__ ebias,
               __half* __restrict__ outp)
{
    extern __shared__ char sm[];
    const uint32_t s0 = smem_u32(sm);
    const int tid = threadIdx.x, w = tid >> 5, l = tid & 31;
    const int qb = 15 - blockIdx.x;          // heavy CTAs first
    const int h = blockIdx.y, b = blockIdx.z;
    const int q0 = qb * 128;
    const size_t hoff = (size_t)(b * NH + h) * NT * NHD;
    const int ntiles = 2 * qb + 2;           // key tiles of 64

    auto issue_kv = [&](int jt2, int bsel2) {
        #pragma unroll
        for (int i = 0; i < 4; i++) {
            const int ck = tid + i * 256;            // 0..1023
            const int arr = ck >> 9;                 // 0=Kh, 1=Vh
            const int row = (ck >> 3) & 63;
            const int seg = ck & 7;
            const size_t go = hoff + (size_t)(jt2 * 64 + row) * NHD + seg * 8;
            const __half* src = (arr == 0) ? kh + go : vh + go;
            cp16(s0 + bsel2 * KVBUF + arr * KVARR + row * FROWB + seg * 16, src);
        }
        CP_COMMIT();
    };

    // prologue: Q (128 rows) -> persistent region, KV(0) -> buf0
    #pragma unroll
    for (int i = 0; i < 4; i++) {
        const int cq = tid + i * 256;                // 0..1023
        const int row = cq >> 3;
        const int seg = cq & 7;
        cp16(s0 + QOFF + row * FROWB + seg * 16,
             qh + hoff + (size_t)(q0 + row) * NHD + seg * 8);
    }
    CP_COMMIT();
    issue_kv(0, 0);

    float O[8][4];
    #pragma unroll
    for (int nt = 0; nt < 8; nt++)
        #pragma unroll
        for (int k = 0; k < 4; k++) O[nt][k] = 0.f;
    float m0 = -INFINITY, m1 = -INFINITY, l0 = 0.f, l1 = 0.f;

    const int r0 = w * 16 + (l >> 2), r1 = r0 + 8;
    const int gq0 = q0 + r0, gq1 = q0 + r1;
    const int gq_max_warp = q0 + w * 16 + 15;
    const int warp_row0   = q0 + w * 16;

    const uint32_t nRow  = (uint32_t)((l & 7) + ((l >> 4) & 1) * 8);
    const uint32_t kColB = (uint32_t)(((l >> 3) & 1) * 16);
    const uint32_t vRowP = (uint32_t)((l & 7) + ((l >> 3) & 1) * 8);
    const uint32_t vColB = (uint32_t)(((l >> 4) & 1) * 16);
    const uint32_t qb0 = s0 + QOFF +
        (uint32_t)(w * 16 + (l & 7) + ((l >> 3) & 1) * 8) * FROWB + ((l >> 4) * 16);

    const __nv_bfloat16* bias0 = ebias + ((size_t)b * NT + gq0) * NT + 2 * (l & 3);
    const __nv_bfloat16* bias1 = ebias + ((size_t)b * NT + gq1) * NT + 2 * (l & 3);

    for (int jt = 0; jt < ntiles; jt++) {
        const int bsel = jt & 1;
        CP_WAIT0();
        __syncthreads();
        if (jt + 1 < ntiles) issue_kv(jt + 1, bsel ^ 1);

        if (jt * 64 > gq_max_warp) continue;   // tile fully above this warp's rows

        // bias prefetch (hidden under QK MMAs)
        uint32_t breg[16];
        #pragma unroll
        for (int nt = 0; nt < 8; nt++) {
            breg[nt]     = *reinterpret_cast<const uint32_t*>(bias0 + jt * 64 + nt * 8);
            breg[8 + nt] = *reinterpret_cast<const uint32_t*>(bias1 + jt * 64 + nt * 8);
        }

        // ---- S = Q K^T (1 pass)
        float acc[8][4];
        #pragma unroll
        for (int nt = 0; nt < 8; nt++)
            #pragma unroll
            for (int k = 0; k < 4; k++) acc[nt][k] = 0.f;

        const uint32_t kb = s0 + bsel * KVBUF;
        #pragma unroll
        for (int ks = 0; ks < 4; ks++) {
            uint32_t qf[4];
            ldsm4(qf, qb0 + ks * 32);
            #pragma unroll
            for (int np = 0; np < 4; np++) {
                uint32_t khf[4];
                ldsm4(khf, kb + (np * 16 + nRow) * FROWB + kColB + ks * 32);
                #pragma unroll
                for (int sub = 0; sub < 2; sub++)
                    mma_f16(acc[np * 2 + sub], qf, &khf[sub * 2]);
            }
        }

        // ---- softmax (log2 domain)
        float mx0 = -INFINITY, mx1 = -INFINITY;
        const bool maskw = (jt * 64 + 63 > warp_row0);
        #pragma unroll
        for (int nt = 0; nt < 8; nt++) {
            float2 bv0 = __bfloat1622float2(*reinterpret_cast<__nv_bfloat162*>(&breg[nt]));
            float2 bv1 = __bfloat1622float2(*reinterpret_cast<__nv_bfloat162*>(&breg[8 + nt]));
            float v0 = acc[nt][0] + bv0.x;
            float v1 = acc[nt][1] + bv0.y;
            float v2 = acc[nt][2] + bv1.x;
            float v3 = acc[nt][3] + bv1.y;
            if (maskw) {
                const int kc = jt * 64 + nt * 8 + 2 * (l & 3);
                if (kc > gq0)     v0 = -1e30f;
                if (kc + 1 > gq0) v1 = -1e30f;
                if (kc > gq1)     v2 = -1e30f;
                if (kc + 1 > gq1) v3 = -1e30f;
            }
            acc[nt][0] = v0; acc[nt][1] = v1; acc[nt][2] = v2; acc[nt][3] = v3;
            mx0 = fmaxf(mx0, fmaxf(v0, v1));
            mx1 = fmaxf(mx1, fmaxf(v2, v3));
        }
        mx0 = fmaxf(mx0, __shfl_xor_sync(0xffffffff, mx0, 1));
        mx0 = fmaxf(mx0, __shfl_xor_sync(0xffffffff, mx0, 2));
        mx1 = fmaxf(mx1, __shfl_xor_sync(0xffffffff, mx1, 1));
        mx1 = fmaxf(mx1, __shfl_xor_sync(0xffffffff, mx1, 2));

        const float mn0 = fmaxf(m0, mx0), mn1 = fmaxf(m1, mx1);
        const float c0 = fexp2(m0 - mn0), c1 = fexp2(m1 - mn1);
        float rs0 = 0.f, rs1 = 0.f;
        #pragma unroll
        for (int nt = 0; nt < 8; nt++) {
            const float p0 = fexp2(acc[nt][0] - mn0);
            const float p1 = fexp2(acc[nt][1] - mn0);
            const float p2 = fexp2(acc[nt][2] - mn1);
            const float p3 = fexp2(acc[nt][3] - mn1);
            acc[nt][0] = p0; acc[nt][1] = p1; acc[nt][2] = p2; acc[nt][3] = p3;
            rs0 += p0 + p1;
            rs1 += p2 + p3;
        }
        rs0 += __shfl_xor_sync(0xffffffff, rs0, 1);
        rs0 += __shfl_xor_sync(0xffffffff, rs0, 2);
        rs1 += __shfl_xor_sync(0xffffffff, rs1, 1);
        rs1 += __shfl_xor_sync(0xffffffff, rs1, 2);
        l0 = l0 * c0 + rs0;
        l1 = l1 * c1 + rs1;
        m0 = mn0; m1 = mn1;
        #pragma unroll
        for (int nt = 0; nt < 8; nt++) {
            O[nt][0] *= c0; O[nt][1] *= c0; O[nt][2] *= c1; O[nt][3] *= c1;
        }

        // ---- O += P V (1 pass)
        const uint32_t vb = kb + KVARR;
        #pragma unroll
        for (int kk = 0; kk < 4; kk++) {
            uint32_t pf[4];
            pf[0] = packh(acc[2 * kk][0], acc[2 * kk][1]);
            pf[1] = packh(acc[2 * kk][2], acc[2 * kk][3]);
            pf[2] = packh(acc[2 * kk + 1][0], acc[2 * kk + 1][1]);
            pf[3] = packh(acc[2 * kk + 1][2], acc[2 * kk + 1][3]);
            #pragma unroll
            for (int nn = 0; nn < 4; nn++) {
                uint32_t vhf[4];
                ldsm4t(vhf, vb + (kk * 16 + vRowP) * FROWB + nn * 32 + vColB);
                #pragma unroll
                for (int sub = 0; sub < 2; sub++)
                    mma_f16(O[nn * 2 + sub], pf, &vhf[sub * 2]);
            }
        }
    }

    // ---- epilogue: O/l -> fp16, [B,T,D] layout
    const float inv0 = 1.f / l0, inv1 = 1.f / l1;
    const size_t a0 = ((size_t)b * NT + gq0) * ND + h * NHD + 2 * (l & 3);
    const size_t a1 = ((size_t)b * NT + gq1) * ND + h * NHD + 2 * (l & 3);
    #pragma unroll
    for (int nt = 0; nt < 8; nt++) {
        *reinterpret_cast<uint32_t*>(outp + a0 + nt * 8) =
            packh(O[nt][0] * inv0, O[nt][1] * inv0);
        *reinterpret_cast<uint32_t*>(outp + a1 + nt * 8) =
            packh(O[nt][2] * inv1, O[nt][3] * inv1);
    }
}

// ---------------------------------------------------------------------------
extern "C" void kernel_launch(void* const* d_in, const int* in_sizes, int n_in,
                              void* d_out, int out_size)
{
    const float* x     = (const float*)d_in[0];
    const float* eb    = (const float*)d_in[1];
    const float* Wqkv  = (const float*)d_in[2];
    const float* bqkv  = (const float*)d_in[3];
    const float* Wout  = (const float*)d_in[4];
    const float* bout  = (const float*)d_in[5];
    float* out = (float*)d_out;

    __half *xh, *wqh, *woh, *ath, *qh, *kh, *vh;
    __nv_bfloat16* ebbf;
    cudaGetSymbolAddress((void**)&xh,  g_x_h);
    cudaGetSymbolAddress((void**)&wqh, g_wq_h);
    cudaGetSymbolAddress((void**)&woh, g_wo_h);
    cudaGetSymbolAddress((void**)&ath, g_att_h);
    cudaGetSymbolAddress((void**)&qh,  g_q_h);
    cudaGetSymbolAddress((void**)&kh,  g_k_h);
    cudaGetSymbolAddress((void**)&vh,  g_v_h);
    cudaGetSymbolAddress((void**)&ebbf, g_eb_bf);

    const int M = NB * NT;   // 8192

    // [0] fused prepass
    prepass_kernel<<<BLK_SPLIT + BLK_TQKV + BLK_TWO, 256>>>(x, Wqkv, Wout, xh, wqh, woh);

    // [1] bias -> bf16 (pre-scaled by log2e)
    bias_to_bf16_kernel<<<(int)(((size_t)NB * NT * NT) / 4 / 256), 256>>>(eb, ebbf);

    const int gemm_smem = 3 * STG_BYTES;   // 61440 -> 2 CTAs/SM
    cudaFuncSetAttribute(gemm_f16<0>, cudaFuncAttributeMaxDynamicSharedMemorySize, gemm_smem);
    cudaFuncSetAttribute(gemm_f16<1>, cudaFuncAttributeMaxDynamicSharedMemorySize, gemm_smem);

    // [2] QKV projection (1-pass fp16), fused per-head split epilogue
    gemm_f16<1><<<dim3(3 * ND / 128, M / 128), 256, gemm_smem>>>(
        xh, wqh, bqkv, nullptr, qh, kh, vh, M, 3 * ND, ND);

    // [3] flash attention (fp16, 16 warps/SM)  <-- ncu profile index 3
    cudaFuncSetAttribute(flash_mma, cudaFuncAttributeMaxDynamicSharedMemorySize, FLASH_SMEM);
    flash_mma<<<dim3(NT / 128, NH, NB), 256, FLASH_SMEM>>>(qh, kh, vh, ebbf, ath);

    // [4] output projection (1-pass fp16, fp32 out + bias)
    gemm_f16<0><<<dim3(ND / 128, M / 128), 256, gemm_smem>>>(
        ath, woh, bout, out, nullptr, nullptr, nullptr, M, ND, ND);
}

// round 15
// speedup vs baseline: 1.0625x; 1.0625x over previous
#include <cuda_runtime.h>
#include <cuda_fp16.h>
#include <math.h>
#include <stdint.h>

#define NB 4
#define NT 2048
#define ND 1024
#define NH 16
#define NHD 64

#define QSCALE 0.1803368801111244f   // 0.125 * log2(e)
#define LOG2E  1.4426950408889634f

// ---------------------------------------------------------------------------
// scratch (allocation-free rule: __device__ globals) — plain fp16 everywhere
// ---------------------------------------------------------------------------
__device__ __align__(256) __half g_x_h[(size_t)NB * NT * ND];
__device__ __align__(256) __half g_wq_h[(size_t)3 * ND * ND];     // Wqkv^T [3D, D]
__device__ __align__(256) __half g_wo_h[(size_t)ND * ND];         // Wout^T [D, D]
__device__ __align__(256) __half g_att_h[(size_t)NB * NT * ND];
// per-head q/k/v: [B,H,T,64] fp16 (q pre-scaled by QSCALE)
__device__ __align__(256) __half g_q_h[(size_t)NB * NH * NT * NHD];
__device__ __align__(256) __half g_k_h[(size_t)NB * NH * NT * NHD];
__device__ __align__(256) __half g_v_h[(size_t)NB * NH * NT * NHD];
// entity bias in fp16, pre-multiplied by log2(e)
__device__ __align__(256) __half g_eb_h[(size_t)NB * NT * NT];

// ---------------------------------------------------------------------------
// PTX helpers (all baseline sm_80+)
// ---------------------------------------------------------------------------
__device__ __forceinline__ uint32_t smem_u32(const void* p) {
    uint32_t a;
    asm("{ .reg .u64 t; cvta.to.shared.u64 t, %1; cvt.u32.u64 %0, t; }" : "=r"(a) : "l"(p));
    return a;
}
__device__ __forceinline__ void ldsm4(uint32_t* r, uint32_t addr) {
    asm volatile("ldmatrix.sync.aligned.m8n8.x4.shared.b16 {%0,%1,%2,%3}, [%4];"
                 : "=r"(r[0]), "=r"(r[1]), "=r"(r[2]), "=r"(r[3]) : "r"(addr));
}
__device__ __forceinline__ void ldsm4t(uint32_t* r, uint32_t addr) {
    asm volatile("ldmatrix.sync.aligned.m8n8.x4.trans.shared.b16 {%0,%1,%2,%3}, [%4];"
                 : "=r"(r[0]), "=r"(r[1]), "=r"(r[2]), "=r"(r[3]) : "r"(addr));
}
__device__ __forceinline__ void mma_f16(float* c, const uint32_t* a, const uint32_t* b) {
    asm volatile(
        "mma.sync.aligned.m16n8k16.row.col.f32.f16.f16.f32 "
        "{%0,%1,%2,%3}, {%4,%5,%6,%7}, {%8,%9}, {%0,%1,%2,%3};"
        : "+f"(c[0]), "+f"(c[1]), "+f"(c[2]), "+f"(c[3])
        : "r"(a[0]), "r"(a[1]), "r"(a[2]), "r"(a[3]), "r"(b[0]), "r"(b[1]));
}
__device__ __forceinline__ void cp16(uint32_t smem, const void* g) {
    asm volatile("cp.async.cg.shared.global [%0], [%1], 16;" :: "r"(smem), "l"(g));
}
#define CP_COMMIT() asm volatile("cp.async.commit_group;" ::: "memory")
#define CP_WAIT1()  asm volatile("cp.async.wait_group 1;" ::: "memory")
#define CP_WAIT0()  asm volatile("cp.async.wait_group 0;" ::: "memory")

__device__ __forceinline__ uint32_t packh(float a, float b) {
    __half2 t = __floats2half2_rn(a, b);
    return *reinterpret_cast<uint32_t*>(&t);
}
// p = ex2.approx.f16x2( packh(a,b) + bias_h2 )
__device__ __forceinline__ uint32_t exp2_biased_h2(float a, float b, uint32_t bias_h2) {
    uint32_t v = packh(a, b);
    __half2 s = __hadd2(*reinterpret_cast<__half2*>(&v),
                        *reinterpret_cast<__half2*>(&bias_h2));
    uint32_t sv = *reinterpret_cast<uint32_t*>(&s);
    uint32_t r;
    asm("ex2.approx.f16x2 %0, %1;" : "=r"(r) : "r"(sv));
    return r;
}

// ---------------------------------------------------------------------------
// fused prepass: x -> fp16 + both weight transposes (fp16)
// ---------------------------------------------------------------------------
#define BLK_SPLIT 32768
#define BLK_TQKV  3072
#define BLK_TWO   1024

__global__ __launch_bounds__(256)
void prepass_kernel(const float* __restrict__ x,
                    const float* __restrict__ Wqkv,
                    const float* __restrict__ Wout,
                    __half* __restrict__ xh,
                    __half* __restrict__ wqh, __half* __restrict__ woh)
{
    __shared__ float t[32][33];
    const int bid = blockIdx.x;
    const int tid = threadIdx.x;

    if (bid < BLK_SPLIT) {
        const int i = bid * 256 + tid;
        xh[i] = __float2half_rn(x[i]);
        return;
    }

    const float* W;
    __half* Th;
    int N, tb;
    if (bid < BLK_SPLIT + BLK_TQKV) {
        tb = bid - BLK_SPLIT; W = Wqkv; Th = wqh; N = 3 * ND;
    } else {
        tb = bid - BLK_SPLIT - BLK_TQKV; W = Wout; Th = woh; N = ND;
    }
    const int K = ND;
    const int n0 = (tb % (N / 32)) * 32;
    const int k0 = (tb / (N / 32)) * 32;
    const int tx = tid & 31, ty = tid >> 5;
    #pragma unroll
    for (int j = 0; j < 32; j += 8)
        t[ty + j][tx] = W[(size_t)(k0 + ty + j) * N + n0 + tx];
    __syncthreads();
    #pragma unroll
    for (int j = 0; j < 32; j += 8)
        Th[(size_t)(n0 + ty + j) * K + k0 + tx] = __float2half_rn(t[tx][ty + j]);
}

// ---------------------------------------------------------------------------
// entity bias fp32 -> fp16 * log2(e)
// ---------------------------------------------------------------------------
__global__ __launch_bounds__(256)
void bias_to_f16_kernel(const float* __restrict__ src, __half* __restrict__ dst)
{
    const size_t i = ((size_t)blockIdx.x * 256 + threadIdx.x) * 4;
    const float4 v = *reinterpret_cast<const float4*>(src + i);
    uint32_t p0 = packh(v.x * LOG2E, v.y * LOG2E);
    uint32_t p1 = packh(v.z * LOG2E, v.w * LOG2E);
    *reinterpret_cast<uint32_t*>(dst + i)     = p0;
    *reinterpret_cast<uint32_t*>(dst + i + 2) = p1;
}

// ---------------------------------------------------------------------------
// fp16 GEMM (1 pass, proven R13): tile 128x128, BK=32, 3-stage, 2 CTAs/SM.
// ---------------------------------------------------------------------------
#define STG_BYTES 20480
#define T_AH 0
#define T_BH 10240

template <int MODE>
__global__ __launch_bounds__(256, 2)
void gemm_f16(const __half* __restrict__ Ah, const __half* __restrict__ Bh,
              const float* __restrict__ bias, float* __restrict__ C,
              __half* __restrict__ qh, __half* __restrict__ kh, __half* __restrict__ vh,
              int M, int N, int K)
{
    extern __shared__ char dynsm[];
    const uint32_t sb0 = smem_u32(dynsm);

    const int tid = threadIdx.x;
    const int wid = tid >> 5;
    const int l   = tid & 31;
    const int wm  = wid >> 1;
    const int wn  = wid & 1;
    const size_t m0 = (size_t)blockIdx.y * 128;
    const size_t n0 = (size_t)blockIdx.x * 128;

    const int r1 = tid >> 2;
    const int r2 = r1 + 64;
    const int cc = (tid & 3);
    const uint32_t sm_off1 = (uint32_t)r1 * 80 + cc * 16;
    const uint32_t sm_off2 = (uint32_t)r2 * 80 + cc * 16;

    const int nchunks = K >> 5;

    auto issue_stage = [&](int c, int buf) {
        const int kc = c << 5;
        const uint32_t sb = sb0 + buf * STG_BYTES;
        cp16(sb + T_AH + sm_off1, Ah + (m0 + r1) * K + kc + cc * 8);
        cp16(sb + T_AH + sm_off2, Ah + (m0 + r2) * K + kc + cc * 8);
        cp16(sb + T_BH + sm_off1, Bh + (n0 + r1) * K + kc + cc * 8);
        cp16(sb + T_BH + sm_off2, Bh + (n0 + r2) * K + kc + cc * 8);
        CP_COMMIT();
    };

    const int aRow = (l & 7) + ((l >> 3) & 1) * 8;
    const int aCol8 = (l >> 4) * 8;
    const int bRow = (l & 7) + ((l >> 4) & 1) * 8;
    const int bCol8 = ((l >> 3) & 1) * 8;

    float acc[2][8][4];
    #pragma unroll
    for (int mt = 0; mt < 2; mt++)
        #pragma unroll
        for (int nt = 0; nt < 8; nt++)
            #pragma unroll
            for (int k = 0; k < 4; k++) acc[mt][nt][k] = 0.f;

    issue_stage(0, 0);
    issue_stage(1, 1);

    for (int c = 0; c < nchunks; c++) {
        if (c == nchunks - 1) { CP_WAIT0(); } else { CP_WAIT1(); }
        __syncthreads();
        if (c + 2 < nchunks) issue_stage(c + 2, (c + 2) % 3);

        const uint32_t sb = sb0 + (c % 3) * STG_BYTES;
        const uint32_t aBase = sb + (uint32_t)(wm * 32 + aRow) * 80 + aCol8 * 2;
        const uint32_t bBase = sb + (uint32_t)(wn * 64 + bRow) * 80 + bCol8 * 2;

        #pragma unroll
        for (int ks = 0; ks < 2; ks++) {
            uint32_t ah[2][4];
            #pragma unroll
            for (int mt = 0; mt < 2; mt++)
                ldsm4(ah[mt], aBase + T_AH + mt * (16 * 80) + ks * 32);
            #pragma unroll
            for (int np = 0; np < 4; np++) {
                uint32_t bh[4];
                ldsm4(bh, bBase + T_BH + np * (16 * 80) + ks * 32);
                #pragma unroll
                for (int mt = 0; mt < 2; mt++)
                    #pragma unroll
                    for (int sub = 0; sub < 2; sub++)
                        mma_f16(acc[mt][np * 2 + sub], ah[mt], &bh[sub * 2]);
            }
        }
        __syncthreads();
    }

    if (MODE == 0) {
        #pragma unroll
        for (int mt = 0; mt < 2; mt++) {
            const size_t row0 = m0 + wm * 32 + mt * 16 + (l >> 2);
            #pragma unroll
            for (int nt = 0; nt < 8; nt++) {
                const size_t col = n0 + wn * 64 + nt * 8 + (l & 3) * 2;
                const float b0 = bias[col], b1 = bias[col + 1];
                float2 v0 = { acc[mt][nt][0] + b0, acc[mt][nt][1] + b1 };
                float2 v1 = { acc[mt][nt][2] + b0, acc[mt][nt][3] + b1 };
                *reinterpret_cast<float2*>(&C[row0 * N + col]) = v0;
                *reinterpret_cast<float2*>(&C[(row0 + 8) * N + col]) = v1;
            }
        }
    } else {
        const int colbase = (int)n0 + wn * 64;
        const int sel = colbase >> 10;             // 0=q,1=k,2=v
        const int head = (colbase >> 6) & 15;
        const float qs = (sel == 0) ? QSCALE : 1.0f;
        __half* dh = (sel == 0) ? qh : (sel == 1) ? kh : vh;
        #pragma unroll
        for (int mt = 0; mt < 2; mt++) {
            const int row0 = (int)m0 + wm * 32 + mt * 16 + (l >> 2);
            const int bb = row0 >> 11;
            const int t0 = row0 & 2047;
            const size_t base = ((size_t)(bb * NH + head) * NT + t0) * NHD;
            #pragma unroll
            for (int nt = 0; nt < 8; nt++) {
                const int col = colbase + nt * 8 + (l & 3) * 2;
                const int d = col & 63;
                const float b0 = bias[col], b1 = bias[col + 1];
                *reinterpret_cast<uint32_t*>(dh + base + d) =
                    packh((acc[mt][nt][0] + b0) * qs, (acc[mt][nt][1] + b1) * qs);
                *reinterpret_cast<uint32_t*>(dh + base + 8 * NHD + d) =
                    packh((acc[mt][nt][2] + b0) * qs, (acc[mt][nt][3] + b1) * qs);
            }
        }
    }
}

// ---------------------------------------------------------------------------
// fp16 flash attention — no-max softmax (exact, overflow-safe by bound) with
// f16x2 exp2.  256 threads, 8 warps, warp M=16, keytile 64, 2 CTAs/SM.
// Per tile: QK MMAs -> pack+HADD2(bias)+ex2.f16x2 -> PV MMAs accumulate.
// l is a per-thread fp32 partial, reduced by 2 shuffles once at the end.
// smem: 2 x 18432 KV (Kh|Vh) + 18432 Q = 55296 B.
// ---------------------------------------------------------------------------
#define FROWB 144
#define KVARR (64 * FROWB)            // 9216
#define KVBUF (2 * KVARR)             // 18432 : Kh|Vh
#define QOFF (2 * KVBUF)              // 36864
#define FLASH_SMEM (QOFF + 128 * FROWB)   // 55296

__global__ __launch_bounds__(256, 2)
void flash_mma(const __half* __restrict__ qh, const __half* __restrict__ kh,
               const __half* __restrict__ vh,
               const __half* __restrict__ ebias,
               __half* __restrict__ outp)
{
    extern __shared__ char sm[];
    const uint32_t s0 = smem_u32(sm);
    const int tid = threadIdx.x, w = tid >> 5, l = tid & 31;
    const int qb = 15 - blockIdx.x;          // heavy CTAs first
    const int h = blockIdx.y, b = blockIdx.z;
    const int q0 = qb * 128;
    const size_t hoff = (size_t)(b * NH + h) * NT * NHD;
    const int ntiles = 2 * qb + 2;           // key tiles of 64

    auto issue_kv = [&](int jt2, int bsel2) {
        #pragma unroll
        for (int i = 0; i < 4; i++) {
            const int ck = tid + i * 256;            // 0..1023
            const int arr = ck >> 9;                 // 0=Kh, 1=Vh
            const int row = (ck >> 3) & 63;
            const int seg = ck & 7;
            const size_t go = hoff + (size_t)(jt2 * 64 + row) * NHD + seg * 8;
            const __half* src = (arr == 0) ? kh + go : vh + go;
            cp16(s0 + bsel2 * KVBUF + arr * KVARR + row * FROWB + seg * 16, src);
        }
        CP_COMMIT();
    };

    // prologue: Q (128 rows) -> persistent region, KV(0) -> buf0
    #pragma unroll
    for (int i = 0; i < 4; i++) {
        const int cq = tid + i * 256;                // 0..1023
        const int row = cq >> 3;
        const int seg = cq & 7;
        cp16(s0 + QOFF + row * FROWB + seg * 16,
             qh + hoff + (size_t)(q0 + row) * NHD + seg * 8);
    }
    CP_COMMIT();
    issue_kv(0, 0);

    float O[8][4];
    #pragma unroll
    for (int nt = 0; nt < 8; nt++)
        #pragma unroll
        for (int k = 0; k < 4; k++) O[nt][k] = 0.f;
    float l0 = 0.f, l1 = 0.f;                // per-thread partial row sums

    const int r0 = w * 16 + (l >> 2), r1 = r0 + 8;
    const int gq0 = q0 + r0, gq1 = q0 + r1;
    const int gq_max_warp = q0 + w * 16 + 15;
    const int warp_row0   = q0 + w * 16;

    const uint32_t nRow  = (uint32_t)((l & 7) + ((l >> 4) & 1) * 8);
    const uint32_t kColB = (uint32_t)(((l >> 3) & 1) * 16);
    const uint32_t vRowP = (uint32_t)((l & 7) + ((l >> 3) & 1) * 8);
    const uint32_t vColB = (uint32_t)(((l >> 4) & 1) * 16);
    const uint32_t qb0 = s0 + QOFF +
        (uint32_t)(w * 16 + (l & 7) + ((l >> 3) & 1) * 8) * FROWB + ((l >> 4) * 16);

    const __half* bias0 = ebias + ((size_t)b * NT + gq0) * NT + 2 * (l & 3);
    const __half* bias1 = ebias + ((size_t)b * NT + gq1) * NT + 2 * (l & 3);

    for (int jt = 0; jt < ntiles; jt++) {
        const int bsel = jt & 1;
        CP_WAIT0();
        __syncthreads();
        if (jt + 1 < ntiles) issue_kv(jt + 1, bsel ^ 1);

        if (jt * 64 > gq_max_warp) continue;   // tile fully above this warp's rows

        // bias prefetch (fp16, pre-scaled log2e) — hidden under QK MMAs
        uint32_t breg[16];
        #pragma unroll
        for (int nt = 0; nt < 8; nt++) {
            breg[nt]     = *reinterpret_cast<const uint32_t*>(bias0 + jt * 64 + nt * 8);
            breg[8 + nt] = *reinterpret_cast<const uint32_t*>(bias1 + jt * 64 + nt * 8);
        }

        // ---- S = Q K^T (1 pass)
        float acc[8][4];
        #pragma unroll
        for (int nt = 0; nt < 8; nt++)
            #pragma unroll
            for (int k = 0; k < 4; k++) acc[nt][k] = 0.f;

        const uint32_t kb = s0 + bsel * KVBUF;
        #pragma unroll
        for (int ks = 0; ks < 4; ks++) {
            uint32_t qf[4];
            ldsm4(qf, qb0 + ks * 32);
            #pragma unroll
            for (int np = 0; np < 4; np++) {
                uint32_t khf[4];
                ldsm4(khf, kb + (np * 16 + nRow) * FROWB + kColB + ks * 32);
                #pragma unroll
                for (int sub = 0; sub < 2; sub++)
                    mma_f16(acc[np * 2 + sub], qf, &khf[sub * 2]);
            }
        }

        // ---- causal mask (diag tiles only): drive masked logits to -inf
        if (jt * 64 + 63 > warp_row0) {
            #pragma unroll
            for (int nt = 0; nt < 8; nt++) {
                const int kc = jt * 64 + nt * 8 + 2 * (l & 3);
                if (kc > gq0)     acc[nt][0] = -1e30f;
                if (kc + 1 > gq0) acc[nt][1] = -1e30f;
                if (kc > gq1)     acc[nt][2] = -1e30f;
                if (kc + 1 > gq1) acc[nt][3] = -1e30f;
            }
        }

        // ---- P = exp2(S + bias) via f16x2, accumulate l (fp32 partials)
        uint32_t parr[16];
        #pragma unroll
        for (int nt = 0; nt < 8; nt++) {
            const uint32_t pA = exp2_biased_h2(acc[nt][0], acc[nt][1], breg[nt]);
            const uint32_t pB = exp2_biased_h2(acc[nt][2], acc[nt][3], breg[8 + nt]);
            parr[2 * nt]     = pA;
            parr[2 * nt + 1] = pB;
            const float2 fA = __half22float2(*reinterpret_cast<const __half2*>(&pA));
            const float2 fB = __half22float2(*reinterpret_cast<const __half2*>(&pB));
            l0 += fA.x + fA.y;
            l1 += fB.x + fB.y;
        }

        // ---- O += P V (1 pass, straight accumulation — no rescale)
        const uint32_t vb = kb + KVARR;
        #pragma unroll
        for (int kk = 0; kk < 4; kk++) {
            uint32_t pf[4];
            pf[0] = parr[2 * (2 * kk)];
            pf[1] = parr[2 * (2 * kk) + 1];
            pf[2] = parr[2 * (2 * kk + 1)];
            pf[3] = parr[2 * (2 * kk + 1) + 1];
            #pragma unroll
            for (int nn = 0; nn < 4; nn++) {
                uint32_t vhf[4];
                ldsm4t(vhf, vb + (kk * 16 + vRowP) * FROWB + nn * 32 + vColB);
                #pragma unroll
                for (int sub = 0; sub < 2; sub++)
                    mma_f16(O[nn * 2 + sub], pf, &vhf[sub * 2]);
            }
        }
    }

    // ---- final row-sum reduction (once) + epilogue
    l0 += __shfl_xor_sync(0xffffffff, l0, 1);
    l0 += __shfl_xor_sync(0xffffffff, l0, 2);
    l1 += __shfl_xor_sync(0xffffffff, l1, 1);
    l1 += __shfl_xor_sync(0xffffffff, l1, 2);
    const float inv0 = 1.f / l0, inv1 = 1.f / l1;
    const size_t a0 = ((size_t)b * NT + gq0) * ND + h * NHD + 2 * (l & 3);
    const size_t a1 = ((size_t)b * NT + gq1) * ND + h * NHD + 2 * (l & 3);
    #pragma unroll
    for (int nt = 0; nt < 8; nt++) {
        *reinterpret_cast<uint32_t*>(outp + a0 + nt * 8) =
            packh(O[nt][0] * inv0, O[nt][1] * inv0);
        *reinterpret_cast<uint32_t*>(outp + a1 + nt * 8) =
            packh(O[nt][2] * inv1, O[nt][3] * inv1);
    }
}

// ---------------------------------------------------------------------------
extern "C" void kernel_launch(void* const* d_in, const int* in_sizes, int n_in,
                              void* d_out, int out_size)
{
    const float* x     = (const float*)d_in[0];
    const float* eb    = (const float*)d_in[1];
    const float* Wqkv  = (const float*)d_in[2];
    const float* bqkv  = (const float*)d_in[3];
    const float* Wout  = (const float*)d_in[4];
    const float* bout  = (const float*)d_in[5];
    float* out = (float*)d_out;

    __half *xh, *wqh, *woh, *ath, *qh, *kh, *vh, *ebh;
    cudaGetSymbolAddress((void**)&xh,  g_x_h);
    cudaGetSymbolAddress((void**)&wqh, g_wq_h);
    cudaGetSymbolAddress((void**)&woh, g_wo_h);
    cudaGetSymbolAddress((void**)&ath, g_att_h);
    cudaGetSymbolAddress((void**)&qh,  g_q_h);
    cudaGetSymbolAddress((void**)&kh,  g_k_h);
    cudaGetSymbolAddress((void**)&vh,  g_v_h);
    cudaGetSymbolAddress((void**)&ebh, g_eb_h);

    const int M = NB * NT;   // 8192

    // [0] fused prepass
    prepass_kernel<<<BLK_SPLIT + BLK_TQKV + BLK_TWO, 256>>>(x, Wqkv, Wout, xh, wqh, woh);

    // [1] bias -> fp16 (pre-scaled by log2e)
    bias_to_f16_kernel<<<(int)(((size_t)NB * NT * NT) / 4 / 256), 256>>>(eb, ebh);

    const int gemm_smem = 3 * STG_BYTES;   // 61440 -> 2 CTAs/SM
    cudaFuncSetAttribute(gemm_f16<0>, cudaFuncAttributeMaxDynamicSharedMemorySize, gemm_smem);
    cudaFuncSetAttribute(gemm_f16<1>, cudaFuncAttributeMaxDynamicSharedMemorySize, gemm_smem);

    // [2] QKV projection (1-pass fp16), fused per-head split epilogue
    gemm_f16<1><<<dim3(3 * ND / 128, M / 128), 256, gemm_smem>>>(
        xh, wqh, bqkv, nullptr, qh, kh, vh, M, 3 * ND, ND);

    // [3] flash attention (no-max softmax, f16x2 exp)  <-- ncu profile index 3
    cudaFuncSetAttribute(flash_mma, cudaFuncAttributeMaxDynamicSharedMemorySize, FLASH_SMEM);
    flash_mma<<<dim3(NT / 128, NH, NB), 256, FLASH_SMEM>>>(qh, kh, vh, ebh, ath);

    // [4] output projection (1-pass fp16, fp32 out + bias)
    gemm_f16<0><<<dim3(ND / 128, M / 128), 256, gemm_smem>>>(
        ath, woh, bout, out, nullptr, nullptr, nullptr, M, ND, ND);
}

// round 16
// speedup vs baseline: 1.0862x; 1.0223x over previous
#include <cuda_runtime.h>
#include <cuda_fp16.h>
#include <math.h>
#include <stdint.h>

#define NB 4
#define NT 2048
#define ND 1024
#define NH 16
#define NHD 64

#define QSCALE 0.1803368801111244f   // 0.125 * log2(e)
#define LOG2E  1.4426950408889634f

// ---------------------------------------------------------------------------
// scratch (allocation-free rule: __device__ globals) — plain fp16 everywhere
// ---------------------------------------------------------------------------
__device__ __align__(256) __half g_x_h[(size_t)NB * NT * ND];
__device__ __align__(256) __half g_wq_h[(size_t)3 * ND * ND];     // Wqkv^T [3D, D]
__device__ __align__(256) __half g_wo_h[(size_t)ND * ND];         // Wout^T [D, D]
__device__ __align__(256) __half g_att_h[(size_t)NB * NT * ND];
// per-head q/k/v: [B,H,T,64] fp16 (q pre-scaled by QSCALE)
__device__ __align__(256) __half g_q_h[(size_t)NB * NH * NT * NHD];
__device__ __align__(256) __half g_k_h[(size_t)NB * NH * NT * NHD];
__device__ __align__(256) __half g_v_h[(size_t)NB * NH * NT * NHD];
// entity bias in fp16, pre-multiplied by log2(e)
__device__ __align__(256) __half g_eb_h[(size_t)NB * NT * NT];

// ---------------------------------------------------------------------------
// PTX helpers (all baseline sm_80+)
// ---------------------------------------------------------------------------
__device__ __forceinline__ uint32_t smem_u32(const void* p) {
    uint32_t a;
    asm("{ .reg .u64 t; cvta.to.shared.u64 t, %1; cvt.u32.u64 %0, t; }" : "=r"(a) : "l"(p));
    return a;
}
__device__ __forceinline__ void ldsm4(uint32_t* r, uint32_t addr) {
    asm volatile("ldmatrix.sync.aligned.m8n8.x4.shared.b16 {%0,%1,%2,%3}, [%4];"
                 : "=r"(r[0]), "=r"(r[1]), "=r"(r[2]), "=r"(r[3]) : "r"(addr));
}
__device__ __forceinline__ void ldsm4t(uint32_t* r, uint32_t addr) {
    asm volatile("ldmatrix.sync.aligned.m8n8.x4.trans.shared.b16 {%0,%1,%2,%3}, [%4];"
                 : "=r"(r[0]), "=r"(r[1]), "=r"(r[2]), "=r"(r[3]) : "r"(addr));
}
__device__ __forceinline__ void mma_f16(float* c, const uint32_t* a, const uint32_t* b) {
    asm volatile(
        "mma.sync.aligned.m16n8k16.row.col.f32.f16.f16.f32 "
        "{%0,%1,%2,%3}, {%4,%5,%6,%7}, {%8,%9}, {%0,%1,%2,%3};"
        : "+f"(c[0]), "+f"(c[1]), "+f"(c[2]), "+f"(c[3])
        : "r"(a[0]), "r"(a[1]), "r"(a[2]), "r"(a[3]), "r"(b[0]), "r"(b[1]));
}
__device__ __forceinline__ void cp16(uint32_t smem, const void* g) {
    asm volatile("cp.async.cg.shared.global [%0], [%1], 16;" :: "r"(smem), "l"(g));
}
#define CP_COMMIT() asm volatile("cp.async.commit_group;" ::: "memory")
#define CP_WAIT1()  asm volatile("cp.async.wait_group 1;" ::: "memory")
#define CP_WAIT0()  asm volatile("cp.async.wait_group 0;" ::: "memory")

__device__ __forceinline__ uint32_t packh(float a, float b) {
    __half2 t = __floats2half2_rn(a, b);
    return *reinterpret_cast<uint32_t*>(&t);
}
// p = ex2.approx.f16x2( packh(a,b) + bias_h2 )
__device__ __forceinline__ uint32_t exp2_biased_h2(float a, float b, uint32_t bias_h2) {
    uint32_t v = packh(a, b);
    __half2 s = __hadd2(*reinterpret_cast<__half2*>(&v),
                        *reinterpret_cast<__half2*>(&bias_h2));
    uint32_t sv = *reinterpret_cast<uint32_t*>(&s);
    uint32_t r;
    asm("ex2.approx.f16x2 %0, %1;" : "=r"(r) : "r"(sv));
    return r;
}

// ---------------------------------------------------------------------------
// fused prepass: x -> fp16 + both weight transposes (fp16)
// ---------------------------------------------------------------------------
#define BLK_SPLIT 32768
#define BLK_TQKV  3072
#define BLK_TWO   1024

__global__ __launch_bounds__(256)
void prepass_kernel(const float* __restrict__ x,
                    const float* __restrict__ Wqkv,
                    const float* __restrict__ Wout,
                    __half* __restrict__ xh,
                    __half* __restrict__ wqh, __half* __restrict__ woh)
{
    __shared__ float t[32][33];
    const int bid = blockIdx.x;
    const int tid = threadIdx.x;

    if (bid < BLK_SPLIT) {
        const int i = bid * 256 + tid;
        xh[i] = __float2half_rn(x[i]);
        return;
    }

    const float* W;
    __half* Th;
    int N, tb;
    if (bid < BLK_SPLIT + BLK_TQKV) {
        tb = bid - BLK_SPLIT; W = Wqkv; Th = wqh; N = 3 * ND;
    } else {
        tb = bid - BLK_SPLIT - BLK_TQKV; W = Wout; Th = woh; N = ND;
    }
    const int K = ND;
    const int n0 = (tb % (N / 32)) * 32;
    const int k0 = (tb / (N / 32)) * 32;
    const int tx = tid & 31, ty = tid >> 5;
    #pragma unroll
    for (int j = 0; j < 32; j += 8)
        t[ty + j][tx] = W[(size_t)(k0 + ty + j) * N + n0 + tx];
    __syncthreads();
    #pragma unroll
    for (int j = 0; j < 32; j += 8)
        Th[(size_t)(n0 + ty + j) * K + k0 + tx] = __float2half_rn(t[tx][ty + j]);
}

// ---------------------------------------------------------------------------
// entity bias fp32 -> fp16 * log2(e)
// ---------------------------------------------------------------------------
__global__ __launch_bounds__(256)
void bias_to_f16_kernel(const float* __restrict__ src, __half* __restrict__ dst)
{
    const size_t i = ((size_t)blockIdx.x * 256 + threadIdx.x) * 4;
    const float4 v = *reinterpret_cast<const float4*>(src + i);
    uint32_t p0 = packh(v.x * LOG2E, v.y * LOG2E);
    uint32_t p1 = packh(v.z * LOG2E, v.w * LOG2E);
    *reinterpret_cast<uint32_t*>(dst + i)     = p0;
    *reinterpret_cast<uint32_t*>(dst + i + 2) = p1;
}

// ---------------------------------------------------------------------------
// fp16 GEMM (1 pass, proven R13): tile 128x128, BK=32, 3-stage, 2 CTAs/SM.
// ---------------------------------------------------------------------------
#define STG_BYTES 20480
#define T_AH 0
#define T_BH 10240

template <int MODE>
__global__ __launch_bounds__(256, 2)
void gemm_f16(const __half* __restrict__ Ah, const __half* __restrict__ Bh,
              const float* __restrict__ bias, float* __restrict__ C,
              __half* __restrict__ qh, __half* __restrict__ kh, __half* __restrict__ vh,
              int M, int N, int K)
{
    extern __shared__ char dynsm[];
    const uint32_t sb0 = smem_u32(dynsm);

    const int tid = threadIdx.x;
    const int wid = tid >> 5;
    const int l   = tid & 31;
    const int wm  = wid >> 1;
    const int wn  = wid & 1;
    const size_t m0 = (size_t)blockIdx.y * 128;
    const size_t n0 = (size_t)blockIdx.x * 128;

    const int r1 = tid >> 2;
    const int r2 = r1 + 64;
    const int cc = (tid & 3);
    const uint32_t sm_off1 = (uint32_t)r1 * 80 + cc * 16;
    const uint32_t sm_off2 = (uint32_t)r2 * 80 + cc * 16;

    const int nchunks = K >> 5;

    auto issue_stage = [&](int c, int buf) {
        const int kc = c << 5;
        const uint32_t sb = sb0 + buf * STG_BYTES;
        cp16(sb + T_AH + sm_off1, Ah + (m0 + r1) * K + kc + cc * 8);
        cp16(sb + T_AH + sm_off2, Ah + (m0 + r2) * K + kc + cc * 8);
        cp16(sb + T_BH + sm_off1, Bh + (n0 + r1) * K + kc + cc * 8);
        cp16(sb + T_BH + sm_off2, Bh + (n0 + r2) * K + kc + cc * 8);
        CP_COMMIT();
    };

    const int aRow = (l & 7) + ((l >> 3) & 1) * 8;
    const int aCol8 = (l >> 4) * 8;
    const int bRow = (l & 7) + ((l >> 4) & 1) * 8;
    const int bCol8 = ((l >> 3) & 1) * 8;

    float acc[2][8][4];
    #pragma unroll
    for (int mt = 0; mt < 2; mt++)
        #pragma unroll
        for (int nt = 0; nt < 8; nt++)
            #pragma unroll
            for (int k = 0; k < 4; k++) acc[mt][nt][k] = 0.f;

    issue_stage(0, 0);
    issue_stage(1, 1);

    for (int c = 0; c < nchunks; c++) {
        if (c == nchunks - 1) { CP_WAIT0(); } else { CP_WAIT1(); }
        __syncthreads();
        if (c + 2 < nchunks) issue_stage(c + 2, (c + 2) % 3);

        const uint32_t sb = sb0 + (c % 3) * STG_BYTES;
        const uint32_t aBase = sb + (uint32_t)(wm * 32 + aRow) * 80 + aCol8 * 2;
        const uint32_t bBase = sb + (uint32_t)(wn * 64 + bRow) * 80 + bCol8 * 2;

        #pragma unroll
        for (int ks = 0; ks < 2; ks++) {
            uint32_t ah[2][4];
            #pragma unroll
            for (int mt = 0; mt < 2; mt++)
                ldsm4(ah[mt], aBase + T_AH + mt * (16 * 80) + ks * 32);
            #pragma unroll
            for (int np = 0; np < 4; np++) {
                uint32_t bh[4];
                ldsm4(bh, bBase + T_BH + np * (16 * 80) + ks * 32);
                #pragma unroll
                for (int mt = 0; mt < 2; mt++)
                    #pragma unroll
                    for (int sub = 0; sub < 2; sub++)
                        mma_f16(acc[mt][np * 2 + sub], ah[mt], &bh[sub * 2]);
            }
        }
        __syncthreads();
    }

    if (MODE == 0) {
        #pragma unroll
        for (int mt = 0; mt < 2; mt++) {
            const size_t row0 = m0 + wm * 32 + mt * 16 + (l >> 2);
            #pragma unroll
            for (int nt = 0; nt < 8; nt++) {
                const size_t col = n0 + wn * 64 + nt * 8 + (l & 3) * 2;
                const float b0 = bias[col], b1 = bias[col + 1];
                float2 v0 = { acc[mt][nt][0] + b0, acc[mt][nt][1] + b1 };
                float2 v1 = { acc[mt][nt][2] + b0, acc[mt][nt][3] + b1 };
                *reinterpret_cast<float2*>(&C[row0 * N + col]) = v0;
                *reinterpret_cast<float2*>(&C[(row0 + 8) * N + col]) = v1;
            }
        }
    } else {
        const int colbase = (int)n0 + wn * 64;
        const int sel = colbase >> 10;             // 0=q,1=k,2=v
        const int head = (colbase >> 6) & 15;
        const float qs = (sel == 0) ? QSCALE : 1.0f;
        __half* dh = (sel == 0) ? qh : (sel == 1) ? kh : vh;
        #pragma unroll
        for (int mt = 0; mt < 2; mt++) {
            const int row0 = (int)m0 + wm * 32 + mt * 16 + (l >> 2);
            const int bb = row0 >> 11;
            const int t0 = row0 & 2047;
            const size_t base = ((size_t)(bb * NH + head) * NT + t0) * NHD;
            #pragma unroll
            for (int nt = 0; nt < 8; nt++) {
                const int col = colbase + nt * 8 + (l & 3) * 2;
                const int d = col & 63;
                const float b0 = bias[col], b1 = bias[col + 1];
                *reinterpret_cast<uint32_t*>(dh + base + d) =
                    packh((acc[mt][nt][0] + b0) * qs, (acc[mt][nt][1] + b1) * qs);
                *reinterpret_cast<uint32_t*>(dh + base + 8 * NHD + d) =
                    packh((acc[mt][nt][2] + b0) * qs, (acc[mt][nt][3] + b1) * qs);
            }
        }
    }
}

// ---------------------------------------------------------------------------
// fp16 flash attention — no-max softmax + warp-M=32 fragment reuse.
// 128 threads, 4 warps, warp M=32 (two m16 tiles share each K/V fragment),
// keytile 64, 2 CTAs/SM. Per-warp causal tile skipping.
// smem: 2 x 18432 KV (Kh|Vh) + 18432 Q = 55296 B.
// ---------------------------------------------------------------------------
#define FROWB 144
#define KVARR (64 * FROWB)            // 9216
#define KVBUF (2 * KVARR)             // 18432 : Kh|Vh
#define QOFF (2 * KVBUF)              // 36864
#define FLASH_SMEM (QOFF + 128 * FROWB)   // 55296

__global__ __launch_bounds__(128, 2)
void flash_mma(const __half* __restrict__ qh, const __half* __restrict__ kh,
               const __half* __restrict__ vh,
               const __half* __restrict__ ebias,
               __half* __restrict__ outp)
{
    extern __shared__ char sm[];
    const uint32_t s0 = smem_u32(sm);
    const int tid = threadIdx.x, w = tid >> 5, l = tid & 31;
    const int qb = 15 - blockIdx.x;          // heavy CTAs first
    const int h = blockIdx.y, b = blockIdx.z;
    const int q0 = qb * 128;
    const size_t hoff = (size_t)(b * NH + h) * NT * NHD;
    const int ntiles = 2 * qb + 2;           // key tiles of 64

    auto issue_kv = [&](int jt2, int bsel2) {
        #pragma unroll
        for (int i = 0; i < 8; i++) {
            const int ck = tid + i * 128;            // 0..1023
            const int arr = ck >> 9;                 // 0=Kh, 1=Vh
            const int row = (ck >> 3) & 63;
            const int seg = ck & 7;
            const size_t go = hoff + (size_t)(jt2 * 64 + row) * NHD + seg * 8;
            const __half* src = (arr == 0) ? kh + go : vh + go;
            cp16(s0 + bsel2 * KVBUF + arr * KVARR + row * FROWB + seg * 16, src);
        }
        CP_COMMIT();
    };

    // prologue: Q (128 rows) -> persistent region, KV(0) -> buf0
    #pragma unroll
    for (int i = 0; i < 8; i++) {
        const int cq = tid + i * 128;                // 0..1023
        const int row = cq >> 3;
        const int seg = cq & 7;
        cp16(s0 + QOFF + row * FROWB + seg * 16,
             qh + hoff + (size_t)(q0 + row) * NHD + seg * 8);
    }
    CP_COMMIT();
    issue_kv(0, 0);

    float O[2][8][4];
    #pragma unroll
    for (int mt = 0; mt < 2; mt++)
        #pragma unroll
        for (int nt = 0; nt < 8; nt++)
            #pragma unroll
            for (int k = 0; k < 4; k++) O[mt][nt][k] = 0.f;
    float ls[4] = {0.f, 0.f, 0.f, 0.f};     // per-thread partial row sums

    // rows: i = mt*2 + half: gq[i] = q0 + w*32 + mt*16 + half*8 + (l>>2)
    int gq[4];
    #pragma unroll
    for (int i = 0; i < 4; i++) gq[i] = q0 + w * 32 + (i >> 1) * 16 + (i & 1) * 8 + (l >> 2);
    const int gq_max_warp = q0 + w * 32 + 31;
    const int warp_row0   = q0 + w * 32;

    const uint32_t nRow  = (uint32_t)((l & 7) + ((l >> 4) & 1) * 8);
    const uint32_t kColB = (uint32_t)(((l >> 3) & 1) * 16);
    const uint32_t vRowP = (uint32_t)((l & 7) + ((l >> 3) & 1) * 8);
    const uint32_t vColB = (uint32_t)(((l >> 4) & 1) * 16);
    const uint32_t qb0 = s0 + QOFF +
        (uint32_t)(w * 32 + (l & 7) + ((l >> 3) & 1) * 8) * FROWB + ((l >> 4) * 16);

    const __half* biasp[4];
    #pragma unroll
    for (int i = 0; i < 4; i++)
        biasp[i] = ebias + ((size_t)b * NT + gq[i]) * NT + 2 * (l & 3);

    for (int jt = 0; jt < ntiles; jt++) {
        const int bsel = jt & 1;
        CP_WAIT0();
        __syncthreads();
        if (jt + 1 < ntiles) issue_kv(jt + 1, bsel ^ 1);

        if (jt * 64 > gq_max_warp) continue;   // tile fully above this warp's rows

        // bias prefetch for both m-tiles (hidden under QK MMAs)
        uint32_t breg[2][16];
        #pragma unroll
        for (int mt = 0; mt < 2; mt++)
            #pragma unroll
            for (int nt = 0; nt < 8; nt++) {
                breg[mt][nt]     = *reinterpret_cast<const uint32_t*>(biasp[mt * 2]     + jt * 64 + nt * 8);
                breg[mt][8 + nt] = *reinterpret_cast<const uint32_t*>(biasp[mt * 2 + 1] + jt * 64 + nt * 8);
            }

        // ---- S = Q K^T (1 pass), K fragments shared by both m-tiles
        float acc[2][8][4];
        #pragma unroll
        for (int mt = 0; mt < 2; mt++)
            #pragma unroll
            for (int nt = 0; nt < 8; nt++)
                #pragma unroll
                for (int k = 0; k < 4; k++) acc[mt][nt][k] = 0.f;

        const uint32_t kb = s0 + bsel * KVBUF;
        #pragma unroll
        for (int ks = 0; ks < 4; ks++) {
            uint32_t qf0[4], qf1[4];
            const uint32_t qa = qb0 + ks * 32;
            ldsm4(qf0, qa);
            ldsm4(qf1, qa + 16 * FROWB);
            #pragma unroll
            for (int np = 0; np < 4; np++) {
                uint32_t khf[4];
                ldsm4(khf, kb + (np * 16 + nRow) * FROWB + kColB + ks * 32);
                #pragma unroll
                for (int sub = 0; sub < 2; sub++) {
                    const int nt = np * 2 + sub;
                    mma_f16(acc[0][nt], qf0, &khf[sub * 2]);
                    mma_f16(acc[1][nt], qf1, &khf[sub * 2]);
                }
            }
        }

        // ---- causal mask (diag region only)
        if (jt * 64 + 63 > warp_row0) {
            #pragma unroll
            for (int mt = 0; mt < 2; mt++)
                #pragma unroll
                for (int nt = 0; nt < 8; nt++) {
                    const int kc = jt * 64 + nt * 8 + 2 * (l & 3);
                    if (kc > gq[mt * 2])         acc[mt][nt][0] = -1e30f;
                    if (kc + 1 > gq[mt * 2])     acc[mt][nt][1] = -1e30f;
                    if (kc > gq[mt * 2 + 1])     acc[mt][nt][2] = -1e30f;
                    if (kc + 1 > gq[mt * 2 + 1]) acc[mt][nt][3] = -1e30f;
                }
        }

        // ---- P = exp2(S + bias) via f16x2, accumulate l partials
        uint32_t parr[2][16];
        #pragma unroll
        for (int mt = 0; mt < 2; mt++)
            #pragma unroll
            for (int nt = 0; nt < 8; nt++) {
                const uint32_t pA = exp2_biased_h2(acc[mt][nt][0], acc[mt][nt][1], breg[mt][nt]);
                const uint32_t pB = exp2_biased_h2(acc[mt][nt][2], acc[mt][nt][3], breg[mt][8 + nt]);
                parr[mt][2 * nt]     = pA;
                parr[mt][2 * nt + 1] = pB;
                const float2 fA = __half22float2(*reinterpret_cast<const __half2*>(&pA));
                const float2 fB = __half22float2(*reinterpret_cast<const __half2*>(&pB));
                ls[mt * 2]     += fA.x + fA.y;
                ls[mt * 2 + 1] += fB.x + fB.y;
            }

        // ---- O += P V (1 pass), V fragments shared by both m-tiles
        const uint32_t vb = kb + KVARR;
        #pragma unroll
        for (int kk = 0; kk < 4; kk++) {
            uint32_t pf0[4], pf1[4];
            pf0[0] = parr[0][2 * (2 * kk)];
            pf0[1] = parr[0][2 * (2 * kk) + 1];
            pf0[2] = parr[0][2 * (2 * kk + 1)];
            pf0[3] = parr[0][2 * (2 * kk + 1) + 1];
            pf1[0] = parr[1][2 * (2 * kk)];
            pf1[1] = parr[1][2 * (2 * kk) + 1];
            pf1[2] = parr[1][2 * (2 * kk + 1)];
            pf1[3] = parr[1][2 * (2 * kk + 1) + 1];
            #pragma unroll
            for (int nn = 0; nn < 4; nn++) {
                uint32_t vhf[4];
                ldsm4t(vhf, vb + (kk * 16 + vRowP) * FROWB + nn * 32 + vColB);
                #pragma unroll
                for (int sub = 0; sub < 2; sub++) {
                    const int nt = nn * 2 + sub;
                    mma_f16(O[0][nt], pf0, &vhf[sub * 2]);
                    mma_f16(O[1][nt], pf1, &vhf[sub * 2]);
                }
            }
        }
    }

    // ---- final row-sum reduction (once) + epilogue
    #pragma unroll
    for (int i = 0; i < 4; i++) {
        ls[i] += __shfl_xor_sync(0xffffffff, ls[i], 1);
        ls[i] += __shfl_xor_sync(0xffffffff, ls[i], 2);
    }
    #pragma unroll
    for (int mt = 0; mt < 2; mt++) {
        const float inv0 = 1.f / ls[mt * 2], inv1 = 1.f / ls[mt * 2 + 1];
        const size_t a0 = ((size_t)b * NT + gq[mt * 2])     * ND + h * NHD + 2 * (l & 3);
        const size_t a1 = ((size_t)b * NT + gq[mt * 2 + 1]) * ND + h * NHD + 2 * (l & 3);
        #pragma unroll
        for (int nt = 0; nt < 8; nt++) {
            *reinterpret_cast<uint32_t*>(outp + a0 + nt * 8) =
                packh(O[mt][nt][0] * inv0, O[mt][nt][1] * inv0);
            *reinterpret_cast<uint32_t*>(outp + a1 + nt * 8) =
                packh(O[mt][nt][2] * inv1, O[mt][nt][3] * inv1);
        }
    }
}

// ---------------------------------------------------------------------------
extern "C" void kernel_launch(void* const* d_in, const int* in_sizes, int n_in,
                              void* d_out, int out_size)
{
    const float* x     = (const float*)d_in[0];
    const float* eb    = (const float*)d_in[1];
    const float* Wqkv  = (const float*)d_in[2];
    const float* bqkv  = (const float*)d_in[3];
    const float* Wout  = (const float*)d_in[4];
    const float* bout  = (const float*)d_in[5];
    float* out = (float*)d_out;

    __half *xh, *wqh, *woh, *ath, *qh, *kh, *vh, *ebh;
    cudaGetSymbolAddress((void**)&xh,  g_x_h);
    cudaGetSymbolAddress((void**)&wqh, g_wq_h);
    cudaGetSymbolAddress((void**)&woh, g_wo_h);
    cudaGetSymbolAddress((void**)&ath, g_att_h);
    cudaGetSymbolAddress((void**)&qh,  g_q_h);
    cudaGetSymbolAddress((void**)&kh,  g_k_h);
    cudaGetSymbolAddress((void**)&vh,  g_v_h);
    cudaGetSymbolAddress((void**)&ebh, g_eb_h);

    const int M = NB * NT;   // 8192

    // [0] fused prepass
    prepass_kernel<<<BLK_SPLIT + BLK_TQKV + BLK_TWO, 256>>>(x, Wqkv, Wout, xh, wqh, woh);

    // [1] bias -> fp16 (pre-scaled by log2e)
    bias_to_f16_kernel<<<(int)(((size_t)NB * NT * NT) / 4 / 256), 256>>>(eb, ebh);

    const int gemm_smem = 3 * STG_BYTES;   // 61440 -> 2 CTAs/SM
    cudaFuncSetAttribute(gemm_f16<0>, cudaFuncAttributeMaxDynamicSharedMemorySize, gemm_smem);
    cudaFuncSetAttribute(gemm_f16<1>, cudaFuncAttributeMaxDynamicSharedMemorySize, gemm_smem);

    // [2] QKV projection (1-pass fp16), fused per-head split epilogue
    gemm_f16<1><<<dim3(3 * ND / 128, M / 128), 256, gemm_smem>>>(
        xh, wqh, bqkv, nullptr, qh, kh, vh, M, 3 * ND, ND);

    // [3] flash attention (no-max softmax, warp-M=32)  <-- ncu profile index 3
    cudaFuncSetAttribute(flash_mma, cudaFuncAttributeMaxDynamicSharedMemorySize, FLASH_SMEM);
    flash_mma<<<dim3(NT / 128, NH, NB), 128, FLASH_SMEM>>>(qh, kh, vh, ebh, ath);

    // [4] output projection (1-pass fp16, fp32 out + bias)
    gemm_f16<0><<<dim3(ND / 128, M / 128), 256, gemm_smem>>>(
        ath, woh, bout, out, nullptr, nullptr, nullptr, M, ND, ND);
}